// round 14
// baseline (speedup 1.0000x reference)
#include <cuda_runtime.h>
#include <cuda_fp16.h>

#define NROWS 8000
#define NPADN 8192            // padded N (64 x 128)
#define NPADM 8064
#define CDIM  256
#define HW    1600
#define MT    128
#define MTILES 63
#define NJOBS  1008           // 2 anchors x 63 mtiles x 8 chunks
#define GRIDC  148
#define NWARPS (GRIDC * 16)   // 2368 global warps
#define ATILE_BYTES  65536
#define BSTAGE_BYTES 65536
#define LAB_BYTES    32768

#define K_EX2A 14.4269504089f    // 10*log2(e)
#define K_EX2B -17.3123404907f   // -12*log2(e)

// ---- dynamic smem map (total 230400 <= 232448) ----
#define SM_AF   0
#define SM_FULL 16
#define SM_FREE 48
#define SM_LAB  1024
#define SM_A    33792
#define SM_B    99328
#define SMEM_TOTAL 230400

// ---------------- device scratch ----------------
__device__ __align__(1024) unsigned char g_Asw[2][(size_t)MTILES * ATILE_BYTES];
__device__ __align__(1024) unsigned char g_Bsw[64ull * BSTAGE_BYTES];
__device__ float g_memlab[NROWS];
__device__ float g_posp[2][NPADM];                    // per-half pos partials
__device__ __align__(1024) float g_alf[2][NPADN];
__device__ float4 g_jpart[(size_t)NJOBS * 4 * 128];
__device__ float2 g_part[2][MTILES];
__device__ int g_acnt[MTILES];                        // A tile ready counters (target 256)
__device__ int g_bcnt[64];                            // B chunk ready counters (target 256)
__device__ int g_lab;                                 // labels ready (target 256)
__device__ int g_combc;                               // combine last-block counter

// ---------------- PTX helpers ----------------
__device__ __forceinline__ unsigned smem_u32(const void* p) {
    unsigned a;
    asm("{ .reg .u64 t; cvta.to.shared.u64 t, %1; cvt.u32.u64 %0, t; }" : "=r"(a) : "l"(p));
    return a;
}
__device__ __forceinline__ float ex2f(float x) {
    float r;
    asm("ex2.approx.ftz.f32 %0, %1;" : "=f"(r) : "f"(x));
    return r;
}
__device__ __forceinline__ int ld_acq(const int* p) {
    int v;
    asm volatile("ld.acquire.gpu.b32 %0, [%1];" : "=r"(v) : "l"(p) : "memory");
    return v;
}
#define SPIN_GE(ptr, tgt) do { while (ld_acq(ptr) < (tgt)) { } } while (0)
#define MBAR_INIT(addr, cnt) \
    asm volatile("mbarrier.init.shared.b64 [%0], %1;" :: "r"(addr), "r"(cnt) : "memory")
#define MBAR_EXPECT_TX(addr, bytes) \
    asm volatile("mbarrier.arrive.expect_tx.shared.b64 _, [%0], %1;" :: "r"(addr), "r"(bytes) : "memory")
#define MBAR_ARRIVE(addr) \
    asm volatile("mbarrier.arrive.shared.b64 _, [%0];" :: "r"(addr) : "memory")
#define MBAR_WAIT(addr, ph) do { \
    unsigned _m = (addr), _p = (ph), _d; \
    asm volatile("{\n\t.reg .pred p;\n\tmbarrier.try_wait.parity.acquire.cta.shared::cta.b64 p, [%1], %2;\n\tselp.b32 %0, 1, 0, p;\n\t}" \
                 : "=r"(_d) : "r"(_m), "r"(_p) : "memory"); \
    if (!_d) { \
        asm volatile("{\n\t.reg .pred P1;\n\tWL%=:\n\tmbarrier.try_wait.parity.acquire.cta.shared::cta.b64 P1, [%0], %1, 0x989680;\n\t@P1 bra.uni WD%=;\n\tbra.uni WL%=;\n\tWD%=:\n\t}" \
                     :: "r"(_m), "r"(_p) : "memory"); \
    } } while (0)
#define BULK_G2S(dst, src, bytes, mbar) \
    asm volatile("cp.async.bulk.shared::cluster.global.mbarrier::complete_tx::bytes [%0], [%1], %2, [%3];" \
                 :: "r"(dst), "l"(src), "r"(bytes), "r"(mbar) : "memory")
#define LDSM4(r, addr) \
    asm volatile("ldmatrix.sync.aligned.m8n8.x4.shared.b16 {%0,%1,%2,%3}, [%4];" \
                 : "=r"((r)[0]), "=r"((r)[1]), "=r"((r)[2]), "=r"((r)[3]) : "r"(addr))
#define MMA_FP16(c, a, b0, b1) \
    asm volatile("mma.sync.aligned.m16n8k16.row.col.f32.f16.f16.f32 " \
                 "{%0,%1,%2,%3}, {%4,%5,%6,%7}, {%8,%9}, {%0,%1,%2,%3};" \
                 : "+f"((c)[0]), "+f"((c)[1]), "+f"((c)[2]), "+f"((c)[3]) \
                 : "r"((a)[0]), "r"((a)[1]), "r"((a)[2]), "r"((a)[3]), "r"(b0), "r"(b1))

__device__ __forceinline__ unsigned pack2(float a, float b) {
    __half2 h = __floats2half2_rn(a, b);
    return *(unsigned*)&h;
}

// fragment-layout byte offset for (row m in tile, channel c0 quad)
__device__ __forceinline__ unsigned frag_off(int m, int c0) {
    const int mt = m >> 4, mi8 = (m >> 3) & 1, mr = m & 7;
    const int kt = c0 >> 4, kh = (c0 >> 3) & 1, kc2 = (c0 >> 2) & 1;
    const int q = kh * 2 + mi8;
    return (unsigned)(((kt * 8 + mt) << 9) + (q << 7) + (mr << 4) + kc2 * 8);
}

// ---------------- clear per-launch flags ----------------
__global__ void clear_flags() {
    const int t = threadIdx.x;
    if (t < MTILES) g_acnt[t] = 0;
    if (t < 64) g_bcnt[t] = 0;
    if (t == 0) { g_lab = 0; g_combc = 0; }
}

// ---------------- fold one element of the PREVIOUS stage's scores ----------------
#define FOLD1(Cp, f, ps) do { \
    const int mi_ = (f) >> 4, nj_ = ((f) >> 2) & 3, e_ = (f) & 3; \
    const int rh_ = e_ >> 1; \
    float sv_ = Cp[mi_][nj_][e_]; \
    float lb_; \
    asm volatile("ld.shared.f32 %0, [%1];" : "=f"(lb_) \
        : "r"(sb + SM_LAB + (unsigned)(((unsigned)(ps) * 128u + wn * 32u + nj_ * 8u + ((lane & 3) << 1) + (e_ & 1)) << 2))); \
    rmx[mi_][rh_] = fmaxf(rmx[mi_][rh_], sv_); \
    float ex_ = ex2f(fmaf(sv_, K_EX2A, K_EX2B)); \
    tal[mi_][rh_] += ex_; \
    t1a[mi_][rh_] = fmaf(ex_, lb_, t1a[mi_][rh_]); \
    Cp[mi_][nj_][e_] = 0.f; \
} while (0)

// one step: prefetch next step's B (warp0 lane0, gated by readiness) + 16 kt of MMA + fold
#define STAGE(tcur, sg, Ccur, Cprv, DOFOLD) do { \
    const int buf_ = (tcur) & 1; \
    if (wid == 0 && lane == 0) { \
        const int nt_ = (tcur) + 1; \
        if (nt_ < nsteps) { \
            if (nt_ >= 2) MBAR_WAIT(sb + SM_FREE + 16 * (nt_ & 1), ((nt_ - 2) >> 1) & 1); \
            const int sgn_ = (((jb + (nt_ >> 3)) & 7) << 3) + (nt_ & 7); \
            SPIN_GE(&g_bcnt[sgn_], 256); \
            MBAR_EXPECT_TX(sb + SM_FULL + 16 * (nt_ & 1), BSTAGE_BYTES); \
            BULK_G2S(sb + SM_B + ((unsigned)(nt_ & 1) << 16), \
                     g_Bsw + (size_t)sgn_ * BSTAGE_BYTES, (unsigned)BSTAGE_BYTES, \
                     sb + SM_FULL + 16 * (nt_ & 1)); \
        } \
    } \
    MBAR_WAIT(sb + SM_FULL + 16 * buf_, ((tcur) >> 1) & 1); \
    const unsigned bbase_ = sb + SM_B + ((unsigned)buf_ << 16) + lanoff; \
    _Pragma("unroll") \
    for (int kt_ = 0; kt_ < 16; kt_++) { \
        unsigned Ar0[4], Ar1[4], Bf0[4], Bf1[4]; \
        LDSM4(Ar0, abase  + (unsigned)((kt_ * 8 + wm * 2 + 0) << 9)); \
        LDSM4(Ar1, abase  + (unsigned)((kt_ * 8 + wm * 2 + 1) << 9)); \
        LDSM4(Bf0, bbase_ + (unsigned)((kt_ * 8 + wn * 2 + 0) << 9)); \
        LDSM4(Bf1, bbase_ + (unsigned)((kt_ * 8 + wn * 2 + 1) << 9)); \
        MMA_FP16(Ccur[0][0], Ar0, Bf0[0], Bf0[1]); \
        MMA_FP16(Ccur[0][1], Ar0, Bf0[2], Bf0[3]); \
        MMA_FP16(Ccur[0][2], Ar0, Bf1[0], Bf1[1]); \
        MMA_FP16(Ccur[0][3], Ar0, Bf1[2], Bf1[3]); \
        MMA_FP16(Ccur[1][0], Ar1, Bf0[0], Bf0[1]); \
        MMA_FP16(Ccur[1][1], Ar1, Bf0[2], Bf0[3]); \
        MMA_FP16(Ccur[1][2], Ar1, Bf1[0], Bf1[1]); \
        MMA_FP16(Ccur[1][3], Ar1, Bf1[2], Bf1[3]); \
        if (DOFOLD) { \
            FOLD1(Cprv, kt_ * 2 + 0, (sg) - 1); \
            FOLD1(Cprv, kt_ * 2 + 1, (sg) - 1); \
        } \
    } \
    if (lane == 0) MBAR_ARRIVE(sb + SM_FREE + 16 * buf_); \
} while (0)

// ---------------- fused: warp-task prep + persistent GEMM ----------------
__global__ __launch_bounds__(512, 1) void contrast_mm(
        const float* __restrict__ f1, const float* __restrict__ f2,
        const float* __restrict__ ul1, const float* __restrict__ ul2,
        const int* __restrict__ sel1, const int* __restrict__ sel2,
        const int* __restrict__ pl1, const int* __restrict__ pl2) {
    extern __shared__ char smem[];
    const unsigned sb = smem_u32(smem);
    const int tid = threadIdx.x, wid = tid >> 5, lane = tid & 31;
    const int c = blockIdx.x;
    const int jb = (c * NJOBS) / GRIDC, je = ((c + 1) * NJOBS) / GRIDC;
    const int nsteps = (je - jb) * 8;

    if (tid == 0) {
        MBAR_INIT(sb + SM_AF, 1);
        MBAR_INIT(sb + SM_FULL + 0, 1);   MBAR_INIT(sb + SM_FULL + 16, 1);
        MBAR_INIT(sb + SM_FREE + 0, 16);  MBAR_INIT(sb + SM_FREE + 16, 16);
    }
    __syncthreads();

    // ================= prep phase (warp-granular, no block syncs) =================
    {
        const int W = c * 16 + wid;   // global warp id 0..2367
        if (W < 256) {                // labels: 256 warps x 32 lanes = 8192 rows
            const int j = W * 32 + lane;
            g_alf[0][j] = (j < NROWS) ? (float)pl1[j] : 0.f;
            g_alf[1][j] = (j < NROWS) ? (float)pl2[j] : 0.f;
            __threadfence();
            if (lane == 0) atomicAdd(&g_lab, 1);
        }
        #pragma unroll 1
        for (int k = 0; k < 7; k++) {
            const int ftask = W + k * NWARPS;          // feat: 16128 tasks
            if (ftask < 2 * NPADM) {
                const int i = ftask >> 1, h = ftask & 1;
                const int c0 = h * 128 + lane * 4;
                float4 x1 = make_float4(0.f, 0.f, 0.f, 0.f), x2 = x1;
                if (i < NROWS) {
                    x1 = *(const float4*)(f1 + i * CDIM + c0);
                    x2 = *(const float4*)(f2 + i * CDIM + c0);
                }
                const unsigned off = frag_off(i & 127, c0);
                unsigned char* ab = g_Asw[0] + (size_t)(i >> 7) * ATILE_BYTES + off;
                *(uint2*)ab = make_uint2(pack2(x1.x, x1.y), pack2(x1.z, x1.w));
                *(uint2*)(ab + (size_t)MTILES * ATILE_BYTES) =
                    make_uint2(pack2(x2.x, x2.y), pack2(x2.z, x2.w));
                float p = x1.x * x2.x + x1.y * x2.y + x1.z * x2.z + x1.w * x2.w;
                #pragma unroll
                for (int o = 16; o > 0; o >>= 1) p += __shfl_xor_sync(0xffffffffu, p, o);
                if (lane == 0 && i < NROWS) g_posp[h][i] = p;
                __threadfence();
                if (lane == 0) atomicAdd(&g_acnt[i >> 7], 1);
            }
            const int gtask = W + k * NWARPS;          // gather: 16384 tasks
            if (gtask < 2 * NPADN) {
                const int j = gtask >> 1, h = gtask & 1;
                const int c0 = h * 128 + lane * 4;
                float x0 = 0.f, xa = 0.f, xb = 0.f, xc = 0.f;
                if (j < NROWS) {
                    int n; const float* ul; const int* pl;
                    if (j < 4000) { n = sel1[j];        ul = ul1; pl = pl1; }
                    else          { n = sel2[j - 4000]; ul = ul2; pl = pl2; }
                    const int b = n / HW, hw = n - b * HW;
                    const float* src = ul + (size_t)(b * CDIM + c0) * HW + hw;
                    x0 = src[0]; xa = src[HW]; xb = src[2 * HW]; xc = src[3 * HW];
                    if (h == 0 && lane == 0) g_memlab[j] = (float)pl[n];
                }
                const unsigned off = frag_off(j & 127, c0);
                *(uint2*)(g_Bsw + (size_t)(j >> 7) * BSTAGE_BYTES + off) =
                    make_uint2(pack2(x0, xa), pack2(xb, xc));
                __threadfence();
                if (lane == 0) atomicAdd(&g_bcnt[j >> 7], 1);
            }
        }
    }

    // ================= GEMM phase =================
    if (tid == 0) {   // prefetch B for step 0 (gated)
        const int sg00 = (jb & 7) * 8;
        SPIN_GE(&g_bcnt[sg00], 256);
        MBAR_EXPECT_TX(sb + SM_FULL + 0, BSTAGE_BYTES);
        BULK_G2S(sb + SM_B, g_Bsw + (size_t)sg00 * BSTAGE_BYTES,
                 (unsigned)BSTAGE_BYTES, sb + SM_FULL + 0);
    }

    const int wm = wid >> 2, wn = wid & 3;
    const unsigned lanoff = (unsigned)(((lane >> 3) << 7) + ((lane & 7) << 4));
    const unsigned abase = sb + SM_A + lanoff;

    float Ca[2][4][4], Cb[2][4][4];
    #pragma unroll
    for (int mi = 0; mi < 2; mi++)
        #pragma unroll
        for (int nj = 0; nj < 4; nj++)
            #pragma unroll
            for (int e = 0; e < 4; e++) { Ca[mi][nj][e] = 0.f; Cb[mi][nj][e] = 0.f; }
    float rmx[2][2], tal[2][2], t1a[2][2];
    #pragma unroll
    for (int mi = 0; mi < 2; mi++)
        #pragma unroll
        for (int rh = 0; rh < 2; rh++) { rmx[mi][rh] = -1e30f; tal[mi][rh] = 0.f; t1a[mi][rh] = 0.f; }

    int aphase = 0, cur_a = -1, cur_mt = -1, t = 0;

    for (int j = jb; j < je; j++) {
        const int a = j / 504, mt = (j % 504) >> 3, ch = j & 7;
        if (a != cur_a || mt != cur_mt) {
            __syncthreads();
            if (tid == 0) {
                SPIN_GE(&g_acnt[mt], 256);
                if (a != cur_a) SPIN_GE(&g_lab, 256);
                const unsigned bytes = (unsigned)ATILE_BYTES + (a != cur_a ? (unsigned)LAB_BYTES : 0u);
                MBAR_EXPECT_TX(sb + SM_AF, bytes);
                BULK_G2S(sb + SM_A, g_Asw[a] + (size_t)mt * ATILE_BYTES,
                         (unsigned)ATILE_BYTES, sb + SM_AF);
                if (a != cur_a)
                    BULK_G2S(sb + SM_LAB, g_alf[a], (unsigned)LAB_BYTES, sb + SM_AF);
            }
            MBAR_WAIT(sb + SM_AF, aphase);
            aphase ^= 1;
            cur_a = a; cur_mt = mt;
        }
        const int sg0 = ch * 8;
        for (int sp = 0; sp < 4; sp++) {
            const bool f0 = (sp > 0);
            STAGE(t,     sg0 + sp * 2,     Ca, Cb, f0);
            STAGE(t + 1, sg0 + sp * 2 + 1, Cb, Ca, true);
            t += 2;
        }
        #pragma unroll
        for (int f = 0; f < 32; f++) FOLD1(Cb, f, sg0 + 7);

        #pragma unroll
        for (int mi = 0; mi < 2; mi++)
            #pragma unroll
            for (int rh = 0; rh < 2; rh++) {
                #pragma unroll
                for (int off = 1; off <= 2; off <<= 1) {
                    rmx[mi][rh] = fmaxf(rmx[mi][rh], __shfl_xor_sync(0xffffffffu, rmx[mi][rh], off));
                    tal[mi][rh] += __shfl_xor_sync(0xffffffffu, tal[mi][rh], off);
                    t1a[mi][rh] += __shfl_xor_sync(0xffffffffu, t1a[mi][rh], off);
                }
            }
        if ((lane & 3) == 0) {
            #pragma unroll
            for (int mi = 0; mi < 2; mi++)
                #pragma unroll
                for (int rh = 0; rh < 2; rh++) {
                    const int rr = wm * 32 + mi * 16 + rh * 8 + (lane >> 2);
                    g_jpart[((size_t)j * 4 + wn) * 128 + rr] =
                        make_float4(rmx[mi][rh], tal[mi][rh], t1a[mi][rh], 0.f);
                }
        }
        #pragma unroll
        for (int mi = 0; mi < 2; mi++)
            #pragma unroll
            for (int rh = 0; rh < 2; rh++) { rmx[mi][rh] = -1e30f; tal[mi][rh] = 0.f; t1a[mi][rh] = 0.f; }
    }
}

// ---------------- combine (+ fused last-block finalize) ----------------
__global__ void combine(const float* __restrict__ plog1, const float* __restrict__ plog2,
                        float* __restrict__ out) {
    __shared__ float sm[4][2];
    __shared__ int is_last;
    const int x = blockIdx.x;            // 0..125
    const int a = x / MTILES, mt = x % MTILES;
    const int row = threadIdx.x;         // 128
    const int lane = row & 31;

    float rmax = -1e30f, tall = 0.f, t1v = 0.f;
    const size_t jbase = ((size_t)a * 504 + (size_t)mt * 8) * 4 * 128;
    #pragma unroll
    for (int ch = 0; ch < 8; ch++)
        #pragma unroll
        for (int wn = 0; wn < 4; wn++) {
            float4 v = g_jpart[jbase + ((size_t)ch * 4 + wn) * 128 + row];
            rmax = fmaxf(rmax, v.x);
            tall += v.y;
            t1v  += v.z;
        }
    tall -= (float)(NPADN - NROWS) * ex2f(K_EX2B);

    float num = 0.f, cnt = 0.f;
    const int i = mt * MT + row;
    if (i < NROWS) {
        float posv = (g_posp[0][i] + g_posp[1][i]) * 10.f;
        float mfull = fmaxf(rmax * 10.f, posv);
        float tsel = (g_memlab[i] == 0.f) ? t1v : (tall - t1v);
        float epos = __expf(posv - mfull);
        float sum = epos + tsel * __expf(12.f - mfull);
        float lossv = -logf(epos / (sum + 1e-8f) + 1e-8f);
        float q1 = plog1[i], q2 = plog2[i];
        float mask = a ? ((q1 > 0.7f && q2 < q1) ? 1.f : 0.f)
                       : ((q2 > 0.7f && q1 < q2) ? 1.f : 0.f);
        num = lossv * mask;
        cnt = mask;
    }
    #pragma unroll
    for (int o = 16; o > 0; o >>= 1) {
        num += __shfl_xor_sync(0xffffffffu, num, o);
        cnt += __shfl_xor_sync(0xffffffffu, cnt, o);
    }
    if (lane == 0) { sm[row >> 5][0] = num; sm[row >> 5][1] = cnt; }
    __syncthreads();
    if (row == 0) {
        float n = sm[0][0] + sm[1][0] + sm[2][0] + sm[3][0];
        float cc = sm[0][1] + sm[1][1] + sm[2][1] + sm[3][1];
        g_part[a][mt] = make_float2(n, cc);
        __threadfence();
        is_last = (atomicAdd(&g_combc, 1) == 2 * MTILES - 1);
    }
    __syncthreads();
    if (is_last) {
        __threadfence();   // acquire: all g_part writes visible
        const int aa = row >> 6, idx = row & 63;
        float n = 0.f, cc = 0.f;
        if (idx < MTILES) { float2 v = g_part[aa][idx]; n = v.x; cc = v.y; }
        #pragma unroll
        for (int o = 16; o > 0; o >>= 1) {
            n += __shfl_xor_sync(0xffffffffu, n, o);
            cc += __shfl_xor_sync(0xffffffffu, cc, o);
        }
        __syncthreads();   // reuse sm
        if (lane == 0) { sm[row >> 5][0] = n; sm[row >> 5][1] = cc; }
        __syncthreads();
        if (row == 0) {
            float n1 = sm[0][0] + sm[1][0], c1 = sm[0][1] + sm[1][1];
            float n2 = sm[2][0] + sm[3][0], c2 = sm[2][1] + sm[3][1];
            out[0] = n1 / (c1 + 1e-12f) + n2 / (c2 + 1e-12f);
        }
    }
}

// ---------------- launch ----------------
extern "C" void kernel_launch(void* const* d_in, const int* in_sizes, int n_in,
                              void* d_out, int out_size) {
    const float* feat1 = (const float*)d_in[0];
    const float* feat2 = (const float*)d_in[1];
    const float* ul1   = (const float*)d_in[2];
    const float* ul2   = (const float*)d_in[3];
    const int*   pl1   = (const int*)d_in[4];
    const int*   pl2   = (const int*)d_in[5];
    const float* plog1 = (const float*)d_in[6];
    const float* plog2 = (const float*)d_in[7];
    const int*   sel1  = (const int*)d_in[8];
    const int*   sel2  = (const int*)d_in[9];
    float* out = (float*)d_out;

    cudaFuncSetAttribute(contrast_mm, cudaFuncAttributeMaxDynamicSharedMemorySize, SMEM_TOTAL);

    clear_flags<<<1, 64>>>();
    contrast_mm<<<GRIDC, 512, SMEM_TOTAL>>>(feat1, feat2, ul1, ul2, sel1, sel2, pl1, pl2);
    combine<<<2 * MTILES, 128>>>(plog1, plog2, out);
}

// round 16
// speedup vs baseline: 1.1779x; 1.1779x over previous
#include <cuda_runtime.h>
#include <cuda_fp16.h>

#define NROWS 8000
#define NPADN 8192            // padded N (64 x 128)
#define CDIM  256
#define HW    1600
#define MT    128
#define MTILES 63
#define NJOBS  1008           // 2 anchors x 63 mtiles x 8 chunks
#define GRIDC  148
#define ATILE_BYTES  65536
#define BSTAGE_BYTES 65536
#define LAB_BYTES    32768

#define K_EX2A 14.4269504089f    // 10*log2(e)
#define K_EX2B -17.3123404907f   // -12*log2(e)

// ---- dynamic smem map (total 230400 <= 232448) ----
#define SM_AF   0
#define SM_FULL 16
#define SM_FREE 48
#define SM_LAB  1024
#define SM_A    33792
#define SM_B    99328
#define SMEM_TOTAL 230400

// ---------------- device scratch ----------------
__device__ __align__(1024) unsigned char g_Asw[2][(size_t)MTILES * ATILE_BYTES];
__device__ __align__(1024) unsigned char g_Bsw[64ull * BSTAGE_BYTES];
__device__ float g_memlab[NROWS];
__device__ float g_pos[NROWS];
__device__ __align__(1024) float g_alf[2][NPADN];
__device__ float4 g_jpart[(size_t)NJOBS * 4 * 128];
__device__ float2 g_part[2][MTILES];
__device__ int g_combc;                               // combine last-block counter

// ---------------- PTX helpers ----------------
__device__ __forceinline__ unsigned smem_u32(const void* p) {
    unsigned a;
    asm("{ .reg .u64 t; cvta.to.shared.u64 t, %1; cvt.u32.u64 %0, t; }" : "=r"(a) : "l"(p));
    return a;
}
__device__ __forceinline__ float ex2f(float x) {
    float r;
    asm("ex2.approx.ftz.f32 %0, %1;" : "=f"(r) : "f"(x));
    return r;
}
#define MBAR_INIT(addr, cnt) \
    asm volatile("mbarrier.init.shared.b64 [%0], %1;" :: "r"(addr), "r"(cnt) : "memory")
#define MBAR_EXPECT_TX(addr, bytes) \
    asm volatile("mbarrier.arrive.expect_tx.shared.b64 _, [%0], %1;" :: "r"(addr), "r"(bytes) : "memory")
#define MBAR_ARRIVE(addr) \
    asm volatile("mbarrier.arrive.shared.b64 _, [%0];" :: "r"(addr) : "memory")
#define MBAR_WAIT(addr, ph) do { \
    unsigned _m = (addr), _p = (ph), _d; \
    asm volatile("{\n\t.reg .pred p;\n\tmbarrier.try_wait.parity.acquire.cta.shared::cta.b64 p, [%1], %2;\n\tselp.b32 %0, 1, 0, p;\n\t}" \
                 : "=r"(_d) : "r"(_m), "r"(_p) : "memory"); \
    if (!_d) { \
        asm volatile("{\n\t.reg .pred P1;\n\tWL%=:\n\tmbarrier.try_wait.parity.acquire.cta.shared::cta.b64 P1, [%0], %1, 0x989680;\n\t@P1 bra.uni WD%=;\n\tbra.uni WL%=;\n\tWD%=:\n\t}" \
                     :: "r"(_m), "r"(_p) : "memory"); \
    } } while (0)
#define BULK_G2S(dst, src, bytes, mbar) \
    asm volatile("cp.async.bulk.shared::cluster.global.mbarrier::complete_tx::bytes [%0], [%1], %2, [%3];" \
                 :: "r"(dst), "l"(src), "r"(bytes), "r"(mbar) : "memory")
#define LDSM4(r, addr) \
    asm volatile("ldmatrix.sync.aligned.m8n8.x4.shared.b16 {%0,%1,%2,%3}, [%4];" \
                 : "=r"((r)[0]), "=r"((r)[1]), "=r"((r)[2]), "=r"((r)[3]) : "r"(addr))
#define MMA_FP16(c, a, b0, b1) \
    asm volatile("mma.sync.aligned.m16n8k16.row.col.f32.f16.f16.f32 " \
                 "{%0,%1,%2,%3}, {%4,%5,%6,%7}, {%8,%9}, {%0,%1,%2,%3};" \
                 : "+f"((c)[0]), "+f"((c)[1]), "+f"((c)[2]), "+f"((c)[3]) \
                 : "r"((a)[0]), "r"((a)[1]), "r"((a)[2]), "r"((a)[3]), "r"(b0), "r"(b1))

__device__ __forceinline__ unsigned pack2(float a, float b) {
    __half2 h = __floats2half2_rn(a, b);   // a -> low half (lower address)
    return *(unsigned*)&h;
}

// ---------------- merged prep (R12-identical + g_combc reset) ----------------
// blocks [0, 2016): feats -> both A tiles (8B stores) + pos dot
// blocks [2016, 4064): gather memory rows -> B stages (8B stores) + labels
__global__ void prep_all(const float* __restrict__ f1, const float* __restrict__ f2,
                         const float* __restrict__ ul1, const float* __restrict__ ul2,
                         const int* __restrict__ sel1, const int* __restrict__ sel2,
                         const int* __restrict__ pl1, const int* __restrict__ pl2) {
    __shared__ float ws[8];
    const int t = threadIdx.x;
    if (blockIdx.x == 0 && t == 0) g_combc = 0;   // reset combine counter (graph-replay-safe)
    const int r = t >> 6, sub = t & 63;
    const int kc2 = sub & 1, kh = (sub >> 1) & 1, kt = sub >> 2;
    const int k0 = kt * 16 + kh * 8 + kc2 * 4;

    if (blockIdx.x < 2016) {
        const int i = blockIdx.x * 4 + r;
        float4 x1 = make_float4(0.f, 0.f, 0.f, 0.f), x2 = x1;
        if (i < NROWS) {
            x1 = *(const float4*)(f1 + i * CDIM + k0);
            x2 = *(const float4*)(f2 + i * CDIM + k0);
        }
        const int tile = i >> 7, m = i & 127;
        const int mt = m >> 4, mi8 = (m >> 3) & 1, mr = m & 7;
        const int q = kh * 2 + mi8;
        const unsigned off = (unsigned)(((kt * 8 + mt) << 9) + (q << 7) + (mr << 4) + kc2 * 8);
        *(uint2*)(g_Asw[0] + (size_t)tile * ATILE_BYTES + off) =
            make_uint2(pack2(x1.x, x1.y), pack2(x1.z, x1.w));
        *(uint2*)(g_Asw[1] + (size_t)tile * ATILE_BYTES + off) =
            make_uint2(pack2(x2.x, x2.y), pack2(x2.z, x2.w));
        float p = x1.x * x2.x + x1.y * x2.y + x1.z * x2.z + x1.w * x2.w;
        #pragma unroll
        for (int o = 16; o > 0; o >>= 1) p += __shfl_xor_sync(0xffffffffu, p, o);
        if ((t & 31) == 0) ws[t >> 5] = p;
        __syncthreads();
        if (sub == 0 && i < NROWS)
            g_pos[i] = (ws[r * 2] + ws[r * 2 + 1]) * 10.f;
    } else {
        const int j = (blockIdx.x - 2016) * 4 + r;   // j < 8192
        float x0 = 0.f, xa = 0.f, xb = 0.f, xc = 0.f;
        if (j < NROWS) {
            int n; const float* ul; const int* pl;
            if (j < 4000) { n = sel1[j];        ul = ul1; pl = pl1; }
            else          { n = sel2[j - 4000]; ul = ul2; pl = pl2; }
            const int b = n / HW, hw = n - b * HW;
            const float* src = ul + (size_t)(b * CDIM + k0) * HW + hw;
            x0 = src[0]; xa = src[HW]; xb = src[2 * HW]; xc = src[3 * HW];
            if (sub == 0) g_memlab[j] = (float)pl[n];
        }
        if (sub == 1) {
            g_alf[0][j] = (j < NROWS) ? (float)pl1[j] : 0.f;
            g_alf[1][j] = (j < NROWS) ? (float)pl2[j] : 0.f;
        }
        const int chunk = j >> 7, nn = j & 127;
        const int nt = nn >> 4, ni8 = (nn >> 3) & 1, nr = nn & 7;
        const int q = ni8 * 2 + kh;
        const unsigned off = (unsigned)(((kt * 8 + nt) << 9) + (q << 7) + (nr << 4) + kc2 * 8);
        *(uint2*)(g_Bsw + (size_t)chunk * BSTAGE_BYTES + off) =
            make_uint2(pack2(x0, xa), pack2(xb, xc));
    }
}

// ---------------- fold one element of the PREVIOUS stage's scores ----------------
#define FOLD1(Cp, f, ps) do { \
    const int mi_ = (f) >> 4, nj_ = ((f) >> 2) & 3, e_ = (f) & 3; \
    const int rh_ = e_ >> 1; \
    float sv_ = Cp[mi_][nj_][e_]; \
    float lb_; \
    asm volatile("ld.shared.f32 %0, [%1];" : "=f"(lb_) \
        : "r"(sb + SM_LAB + (unsigned)(((unsigned)(ps) * 128u + wn * 32u + nj_ * 8u + ((lane & 3) << 1) + (e_ & 1)) << 2))); \
    rmx[mi_][rh_] = fmaxf(rmx[mi_][rh_], sv_); \
    float ex_ = ex2f(fmaf(sv_, K_EX2A, K_EX2B)); \
    tal[mi_][rh_] += ex_; \
    t1a[mi_][rh_] = fmaf(ex_, lb_, t1a[mi_][rh_]); \
    Cp[mi_][nj_][e_] = 0.f; \
} while (0)

// one step: prefetch next step's B (warp0 lane0) + 16 kt of MMA + interleaved fold
#define STAGE(tcur, sg, Ccur, Cprv, DOFOLD) do { \
    const int buf_ = (tcur) & 1; \
    if (wid == 0 && lane == 0) { \
        const int nt_ = (tcur) + 1; \
        if (nt_ < nsteps) { \
            if (nt_ >= 2) MBAR_WAIT(sb + SM_FREE + 16 * (nt_ & 1), ((nt_ - 2) >> 1) & 1); \
            MBAR_EXPECT_TX(sb + SM_FULL + 16 * (nt_ & 1), BSTAGE_BYTES); \
            const int sgn_ = (((jb + (nt_ >> 3)) & 7) << 3) + (nt_ & 7); \
            BULK_G2S(sb + SM_B + ((unsigned)(nt_ & 1) << 16), \
                     g_Bsw + (size_t)sgn_ * BSTAGE_BYTES, (unsigned)BSTAGE_BYTES, \
                     sb + SM_FULL + 16 * (nt_ & 1)); \
        } \
    } \
    MBAR_WAIT(sb + SM_FULL + 16 * buf_, ((tcur) >> 1) & 1); \
    const unsigned bbase_ = sb + SM_B + ((unsigned)buf_ << 16) + lanoff; \
    _Pragma("unroll") \
    for (int kt_ = 0; kt_ < 16; kt_++) { \
        unsigned Ar0[4], Ar1[4], Bf0[4], Bf1[4]; \
        LDSM4(Ar0, abase  + (unsigned)((kt_ * 8 + wm * 2 + 0) << 9)); \
        LDSM4(Ar1, abase  + (unsigned)((kt_ * 8 + wm * 2 + 1) << 9)); \
        LDSM4(Bf0, bbase_ + (unsigned)((kt_ * 8 + wn * 2 + 0) << 9)); \
        LDSM4(Bf1, bbase_ + (unsigned)((kt_ * 8 + wn * 2 + 1) << 9)); \
        MMA_FP16(Ccur[0][0], Ar0, Bf0[0], Bf0[1]); \
        MMA_FP16(Ccur[0][1], Ar0, Bf0[2], Bf0[3]); \
        MMA_FP16(Ccur[0][2], Ar0, Bf1[0], Bf1[1]); \
        MMA_FP16(Ccur[0][3], Ar0, Bf1[2], Bf1[3]); \
        MMA_FP16(Ccur[1][0], Ar1, Bf0[0], Bf0[1]); \
        MMA_FP16(Ccur[1][1], Ar1, Bf0[2], Bf0[3]); \
        MMA_FP16(Ccur[1][2], Ar1, Bf1[0], Bf1[1]); \
        MMA_FP16(Ccur[1][3], Ar1, Bf1[2], Bf1[3]); \
        if (DOFOLD) { \
            FOLD1(Cprv, kt_ * 2 + 0, (sg) - 1); \
            FOLD1(Cprv, kt_ * 2 + 1, (sg) - 1); \
        } \
    } \
    if (lane == 0) MBAR_ARRIVE(sb + SM_FREE + 16 * buf_); \
} while (0)

// ---------------- main: persistent 148-CTA GEMM over 1008 jobs (R12-identical) ----------------
__global__ __launch_bounds__(512, 1) void contrast_mm() {
    extern __shared__ char smem[];
    const unsigned sb = smem_u32(smem);
    const int tid = threadIdx.x, wid = tid >> 5, lane = tid & 31;
    const int c = blockIdx.x;
    const int jb = (c * NJOBS) / GRIDC, je = ((c + 1) * NJOBS) / GRIDC;
    const int nsteps = (je - jb) * 8;

    if (tid == 0) {
        MBAR_INIT(sb + SM_AF, 1);
        MBAR_INIT(sb + SM_FULL + 0, 1);   MBAR_INIT(sb + SM_FULL + 16, 1);
        MBAR_INIT(sb + SM_FREE + 0, 16);  MBAR_INIT(sb + SM_FREE + 16, 16);
    }
    __syncthreads();
    if (tid == 0) {   // prefetch B for step 0
        MBAR_EXPECT_TX(sb + SM_FULL + 0, BSTAGE_BYTES);
        BULK_G2S(sb + SM_B, g_Bsw + (size_t)((jb & 7) * 8) * BSTAGE_BYTES,
                 (unsigned)BSTAGE_BYTES, sb + SM_FULL + 0);
    }

    const int wm = wid >> 2, wn = wid & 3;   // 4 M-warps x 4 N-warps, tile 32x32
    const unsigned lanoff = (unsigned)(((lane >> 3) << 7) + ((lane & 7) << 4));
    const unsigned abase = sb + SM_A + lanoff;

    float Ca[2][4][4], Cb[2][4][4];
    #pragma unroll
    for (int mi = 0; mi < 2; mi++)
        #pragma unroll
        for (int nj = 0; nj < 4; nj++)
            #pragma unroll
            for (int e = 0; e < 4; e++) { Ca[mi][nj][e] = 0.f; Cb[mi][nj][e] = 0.f; }
    float rmx[2][2], tal[2][2], t1a[2][2];
    #pragma unroll
    for (int mi = 0; mi < 2; mi++)
        #pragma unroll
        for (int rh = 0; rh < 2; rh++) { rmx[mi][rh] = -1e30f; tal[mi][rh] = 0.f; t1a[mi][rh] = 0.f; }

    int aphase = 0, cur_a = -1, cur_mt = -1, t = 0;

    for (int j = jb; j < je; j++) {
        const int a = j / 504, mt = (j % 504) >> 3, ch = j & 7;
        if (a != cur_a || mt != cur_mt) {
            __syncthreads();
            if (tid == 0) {
                const unsigned bytes = (unsigned)ATILE_BYTES + (a != cur_a ? (unsigned)LAB_BYTES : 0u);
                MBAR_EXPECT_TX(sb + SM_AF, bytes);
                BULK_G2S(sb + SM_A, g_Asw[a] + (size_t)mt * ATILE_BYTES,
                         (unsigned)ATILE_BYTES, sb + SM_AF);
                if (a != cur_a)
                    BULK_G2S(sb + SM_LAB, g_alf[a], (unsigned)LAB_BYTES, sb + SM_AF);
            }
            MBAR_WAIT(sb + SM_AF, aphase);
            aphase ^= 1;
            cur_a = a; cur_mt = mt;
        }
        const int sg0 = ch * 8;
        for (int sp = 0; sp < 4; sp++) {
            const bool f0 = (sp > 0);
            STAGE(t,     sg0 + sp * 2,     Ca, Cb, f0);
            STAGE(t + 1, sg0 + sp * 2 + 1, Cb, Ca, true);
            t += 2;
        }
        #pragma unroll
        for (int f = 0; f < 32; f++) FOLD1(Cb, f, sg0 + 7);

        #pragma unroll
        for (int mi = 0; mi < 2; mi++)
            #pragma unroll
            for (int rh = 0; rh < 2; rh++) {
                #pragma unroll
                for (int off = 1; off <= 2; off <<= 1) {
                    rmx[mi][rh] = fmaxf(rmx[mi][rh], __shfl_xor_sync(0xffffffffu, rmx[mi][rh], off));
                    tal[mi][rh] += __shfl_xor_sync(0xffffffffu, tal[mi][rh], off);
                    t1a[mi][rh] += __shfl_xor_sync(0xffffffffu, t1a[mi][rh], off);
                }
            }
        if ((lane & 3) == 0) {
            #pragma unroll
            for (int mi = 0; mi < 2; mi++)
                #pragma unroll
                for (int rh = 0; rh < 2; rh++) {
                    const int rr = wm * 32 + mi * 16 + rh * 8 + (lane >> 2);
                    g_jpart[((size_t)j * 4 + wn) * 128 + rr] =
                        make_float4(rmx[mi][rh], tal[mi][rh], t1a[mi][rh], 0.f);
                }
        }
        #pragma unroll
        for (int mi = 0; mi < 2; mi++)
            #pragma unroll
            for (int rh = 0; rh < 2; rh++) { rmx[mi][rh] = -1e30f; tal[mi][rh] = 0.f; t1a[mi][rh] = 0.f; }
    }
}

// ---------------- combine (+ fused last-block finalize) ----------------
__global__ void combine(const float* __restrict__ plog1, const float* __restrict__ plog2,
                        float* __restrict__ out) {
    __shared__ float sm[4][2];
    __shared__ int is_last;
    const int x = blockIdx.x;            // 0..125
    const int a = x / MTILES, mt = x % MTILES;
    const int row = threadIdx.x;         // 128
    const int lane = row & 31;

    float rmax = -1e30f, tall = 0.f, t1v = 0.f;
    const size_t jbase = ((size_t)a * 504 + (size_t)mt * 8) * 4 * 128;
    #pragma unroll
    for (int ch = 0; ch < 8; ch++)
        #pragma unroll
        for (int wn = 0; wn < 4; wn++) {
            float4 v = g_jpart[jbase + ((size_t)ch * 4 + wn) * 128 + row];
            rmax = fmaxf(rmax, v.x);
            tall += v.y;
            t1v  += v.z;
        }
    tall -= (float)(NPADN - NROWS) * ex2f(K_EX2B);

    float num = 0.f, cnt = 0.f;
    const int i = mt * MT + row;
    if (i < NROWS) {
        float posv = g_pos[i];
        float mfull = fmaxf(rmax * 10.f, posv);
        float tsel = (g_memlab[i] == 0.f) ? t1v : (tall - t1v);
        float epos = __expf(posv - mfull);
        float sum = epos + tsel * __expf(12.f - mfull);
        float lossv = -logf(epos / (sum + 1e-8f) + 1e-8f);
        float q1 = plog1[i], q2 = plog2[i];
        float mask = a ? ((q1 > 0.7f && q2 < q1) ? 1.f : 0.f)
                       : ((q2 > 0.7f && q1 < q2) ? 1.f : 0.f);
        num = lossv * mask;
        cnt = mask;
    }
    #pragma unroll
    for (int o = 16; o > 0; o >>= 1) {
        num += __shfl_xor_sync(0xffffffffu, num, o);
        cnt += __shfl_xor_sync(0xffffffffu, cnt, o);
    }
    if (lane == 0) { sm[row >> 5][0] = num; sm[row >> 5][1] = cnt; }
    __syncthreads();
    if (row == 0) {
        float n = sm[0][0] + sm[1][0] + sm[2][0] + sm[3][0];
        float cc = sm[0][1] + sm[1][1] + sm[2][1] + sm[3][1];
        g_part[a][mt] = make_float2(n, cc);
        __threadfence();
        is_last = (atomicAdd(&g_combc, 1) == 2 * MTILES - 1);
    }
    __syncthreads();
    if (is_last) {
        __threadfence();   // acquire: all g_part writes visible
        const int aa = row >> 6, idx = row & 63;
        float n = 0.f, cc = 0.f;
        if (idx < MTILES) { float2 v = g_part[aa][idx]; n = v.x; cc = v.y; }
        #pragma unroll
        for (int o = 16; o > 0; o >>= 1) {
            n += __shfl_xor_sync(0xffffffffu, n, o);
            cc += __shfl_xor_sync(0xffffffffu, cc, o);
        }
        __syncthreads();
        if (lane == 0) { sm[row >> 5][0] = n; sm[row >> 5][1] = cc; }
        __syncthreads();
        if (row == 0) {
            float n1 = sm[0][0] + sm[1][0], c1 = sm[0][1] + sm[1][1];
            float n2 = sm[2][0] + sm[3][0], c2 = sm[2][1] + sm[3][1];
            out[0] = n1 / (c1 + 1e-12f) + n2 / (c2 + 1e-12f);
        }
    }
}

// ---------------- launch ----------------
extern "C" void kernel_launch(void* const* d_in, const int* in_sizes, int n_in,
                              void* d_out, int out_size) {
    const float* feat1 = (const float*)d_in[0];
    const float* feat2 = (const float*)d_in[1];
    const float* ul1   = (const float*)d_in[2];
    const float* ul2   = (const float*)d_in[3];
    const int*   pl1   = (const int*)d_in[4];
    const int*   pl2   = (const int*)d_in[5];
    const float* plog1 = (const float*)d_in[6];
    const float* plog2 = (const float*)d_in[7];
    const int*   sel1  = (const int*)d_in[8];
    const int*   sel2  = (const int*)d_in[9];
    float* out = (float*)d_out;

    cudaFuncSetAttribute(contrast_mm, cudaFuncAttributeMaxDynamicSharedMemorySize, SMEM_TOTAL);

    prep_all<<<4064, 256>>>(feat1, feat2, ul1, ul2, sel1, sel2, pl1, pl2);
    contrast_mm<<<GRIDC, 512, SMEM_TOTAL>>>();
    combine<<<2 * MTILES, 128>>>(plog1, plog2, out);
}

// round 17
// speedup vs baseline: 1.1938x; 1.0135x over previous
#include <cuda_runtime.h>
#include <cuda_fp16.h>

#define NROWS 8000
#define NPADN 8192            // padded N (64 x 128)
#define CDIM  256
#define HW    1600
#define MT    128
#define MTILES 63
#define NJOBS  1008           // 2 anchors x 63 mtiles x 8 chunks
#define GRIDC  148
#define ATILE_BYTES  65536
#define BSTAGE_BYTES 65536
#define LAB_BYTES    32768

#define K_EX2A 14.4269504089f    // 10*log2(e)
#define K_EX2B -17.3123404907f   // -12*log2(e)

// ---- dynamic smem map (total 230400 <= 232448) ----
#define SM_AF   0
#define SM_FULL 16
#define SM_FREE 48
#define SM_LAB  1024
#define SM_A    33792
#define SM_B    99328
#define SMEM_TOTAL 230400

// ---------------- device scratch ----------------
__device__ __align__(1024) unsigned char g_Asw[2][(size_t)MTILES * ATILE_BYTES];
__device__ __align__(1024) unsigned char g_Bsw[64ull * BSTAGE_BYTES];
__device__ __align__(1024) float g_ulT[2][(size_t)NROWS * CDIM];   // transposed ul: [n][c]
__device__ float g_memlab[NROWS];
__device__ float g_pos[NROWS];
__device__ __align__(1024) float g_alf[2][NPADN];
__device__ float4 g_jpart[(size_t)NJOBS * 4 * 128];
__device__ float2 g_part[2][MTILES];
__device__ int g_combc;                               // combine last-block counter

// ---------------- PTX helpers ----------------
__device__ __forceinline__ unsigned smem_u32(const void* p) {
    unsigned a;
    asm("{ .reg .u64 t; cvta.to.shared.u64 t, %1; cvt.u32.u64 %0, t; }" : "=r"(a) : "l"(p));
    return a;
}
__device__ __forceinline__ float ex2f(float x) {
    float r;
    asm("ex2.approx.ftz.f32 %0, %1;" : "=f"(r) : "f"(x));
    return r;
}
#define MBAR_INIT(addr, cnt) \
    asm volatile("mbarrier.init.shared.b64 [%0], %1;" :: "r"(addr), "r"(cnt) : "memory")
#define MBAR_EXPECT_TX(addr, bytes) \
    asm volatile("mbarrier.arrive.expect_tx.shared.b64 _, [%0], %1;" :: "r"(addr), "r"(bytes) : "memory")
#define MBAR_ARRIVE(addr) \
    asm volatile("mbarrier.arrive.shared.b64 _, [%0];" :: "r"(addr) : "memory")
#define MBAR_WAIT(addr, ph) do { \
    unsigned _m = (addr), _p = (ph), _d; \
    asm volatile("{\n\t.reg .pred p;\n\tmbarrier.try_wait.parity.acquire.cta.shared::cta.b64 p, [%1], %2;\n\tselp.b32 %0, 1, 0, p;\n\t}" \
                 : "=r"(_d) : "r"(_m), "r"(_p) : "memory"); \
    if (!_d) { \
        asm volatile("{\n\t.reg .pred P1;\n\tWL%=:\n\tmbarrier.try_wait.parity.acquire.cta.shared::cta.b64 P1, [%0], %1, 0x989680;\n\t@P1 bra.uni WD%=;\n\tbra.uni WL%=;\n\tWD%=:\n\t}" \
                     :: "r"(_m), "r"(_p) : "memory"); \
    } } while (0)
#define BULK_G2S(dst, src, bytes, mbar) \
    asm volatile("cp.async.bulk.shared::cluster.global.mbarrier::complete_tx::bytes [%0], [%1], %2, [%3];" \
                 :: "r"(dst), "l"(src), "r"(bytes), "r"(mbar) : "memory")
#define LDSM4(r, addr) \
    asm volatile("ldmatrix.sync.aligned.m8n8.x4.shared.b16 {%0,%1,%2,%3}, [%4];" \
                 : "=r"((r)[0]), "=r"((r)[1]), "=r"((r)[2]), "=r"((r)[3]) : "r"(addr))
#define MMA_FP16(c, a, b0, b1) \
    asm volatile("mma.sync.aligned.m16n8k16.row.col.f32.f16.f16.f32 " \
                 "{%0,%1,%2,%3}, {%4,%5,%6,%7}, {%8,%9}, {%0,%1,%2,%3};" \
                 : "+f"((c)[0]), "+f"((c)[1]), "+f"((c)[2]), "+f"((c)[3]) \
                 : "r"((a)[0]), "r"((a)[1]), "r"((a)[2]), "r"((a)[3]), "r"(b0), "r"(b1))

__device__ __forceinline__ unsigned pack2(float a, float b) {
    __half2 h = __floats2half2_rn(a, b);   // a -> low half (lower address)
    return *(unsigned*)&h;
}

// ---------------- prep1: feats->A tiles + pos | ul transpose | labels+memlab ----------------
// blocks [0, 2016): feats (4 rows each) -> both A tiles + pos dot
// blocks [2016, 6016): 32x32 coalesced transpose ul -> g_ulT
// blocks [6016, 6048): labels + memory labels
__global__ void prep1(const float* __restrict__ f1, const float* __restrict__ f2,
                      const float* __restrict__ ul1, const float* __restrict__ ul2,
                      const int* __restrict__ sel1, const int* __restrict__ sel2,
                      const int* __restrict__ pl1, const int* __restrict__ pl2) {
    const int t = threadIdx.x;
    if (blockIdx.x == 0 && t == 0) g_combc = 0;   // reset combine counter (graph-replay-safe)

    if (blockIdx.x < 2016) {
        // ---- feats -> fragment-tiled A + pos (R16-identical) ----
        __shared__ float ws[8];
        const int r = t >> 6, sub = t & 63;
        const int kc2 = sub & 1, kh = (sub >> 1) & 1, kt = sub >> 2;
        const int k0 = kt * 16 + kh * 8 + kc2 * 4;
        const int i = blockIdx.x * 4 + r;
        float4 x1 = make_float4(0.f, 0.f, 0.f, 0.f), x2 = x1;
        if (i < NROWS) {
            x1 = *(const float4*)(f1 + i * CDIM + k0);
            x2 = *(const float4*)(f2 + i * CDIM + k0);
        }
        const int tile = i >> 7, m = i & 127;
        const int mt = m >> 4, mi8 = (m >> 3) & 1, mr = m & 7;
        const int q = kh * 2 + mi8;
        const unsigned off = (unsigned)(((kt * 8 + mt) << 9) + (q << 7) + (mr << 4) + kc2 * 8);
        *(uint2*)(g_Asw[0] + (size_t)tile * ATILE_BYTES + off) =
            make_uint2(pack2(x1.x, x1.y), pack2(x1.z, x1.w));
        *(uint2*)(g_Asw[1] + (size_t)tile * ATILE_BYTES + off) =
            make_uint2(pack2(x2.x, x2.y), pack2(x2.z, x2.w));
        float p = x1.x * x2.x + x1.y * x2.y + x1.z * x2.z + x1.w * x2.w;
        #pragma unroll
        for (int o = 16; o > 0; o >>= 1) p += __shfl_xor_sync(0xffffffffu, p, o);
        if ((t & 31) == 0) ws[t >> 5] = p;
        __syncthreads();
        if (sub == 0 && i < NROWS)
            g_pos[i] = (ws[r * 2] + ws[r * 2 + 1]) * 10.f;
    } else if (blockIdx.x < 6016) {
        // ---- coalesced 32x32 transpose: ul[b][c][hw] -> g_ulT[a][b*HW+hw][c] ----
        __shared__ float sm[32][33];
        const int tr = blockIdx.x - 2016;          // 0..3999
        const int a  = tr / 2000;
        const int r2 = tr - a * 2000;              // 0..1999
        const int b  = r2 / 400;
        const int r3 = r2 - b * 400;               // 0..399
        const int c0 = (r3 / 50) * 32;
        const int hw0 = (r3 % 50) * 32;
        const float* __restrict__ ul = a ? ul2 : ul1;
        const int tx = t & 31, ty = t >> 5;        // ty 0..7
        #pragma unroll
        for (int cc = 0; cc < 4; cc++) {
            const int c = c0 + ty + cc * 8;
            sm[ty + cc * 8][tx] = ul[((size_t)(b * CDIM + c)) * HW + hw0 + tx];
        }
        __syncthreads();
        float* dst = g_ulT[a];
        #pragma unroll
        for (int cc = 0; cc < 4; cc++) {
            const int hw = hw0 + ty + cc * 8;
            dst[((size_t)(b * HW + hw)) * CDIM + c0 + tx] = sm[tx][ty + cc * 8];
        }
    } else {
        // ---- labels + memory labels ----
        const int j = (blockIdx.x - 6016) * 256 + t;   // 0..8191
        g_alf[0][j] = (j < NROWS) ? (float)pl1[j] : 0.f;
        g_alf[1][j] = (j < NROWS) ? (float)pl2[j] : 0.f;
        if (j < NROWS) {
            int n; const int* pl;
            if (j < 4000) { n = sel1[j];        pl = pl1; }
            else          { n = sel2[j - 4000]; pl = pl2; }
            g_memlab[j] = (float)pl[n];
        }
    }
}

// ---------------- prep2: gather transposed rows -> fragment-tiled B stages ----------------
__global__ void prep_B(const int* __restrict__ sel1, const int* __restrict__ sel2) {
    const int t = threadIdx.x;
    const int r = t >> 6, sub = t & 63;
    const int kc2 = sub & 1, kh = (sub >> 1) & 1, kt = sub >> 2;
    const int k0 = kt * 16 + kh * 8 + kc2 * 4;
    const int j = blockIdx.x * 4 + r;              // 0..8191
    float4 x = make_float4(0.f, 0.f, 0.f, 0.f);
    if (j < NROWS) {
        int n; const float* base;
        if (j < 4000) { n = sel1[j];        base = g_ulT[0]; }
        else          { n = sel2[j - 4000]; base = g_ulT[1]; }
        x = *(const float4*)(base + (size_t)n * CDIM + k0);   // contiguous 16B from 1KB row
    }
    const int chunk = j >> 7, nn = j & 127;
    const int nt = nn >> 4, ni8 = (nn >> 3) & 1, nr = nn & 7;
    const int q = ni8 * 2 + kh;
    const unsigned off = (unsigned)(((kt * 8 + nt) << 9) + (q << 7) + (nr << 4) + kc2 * 8);
    *(uint2*)(g_Bsw + (size_t)chunk * BSTAGE_BYTES + off) =
        make_uint2(pack2(x.x, x.y), pack2(x.z, x.w));
}

// ---------------- fold one element of the PREVIOUS stage's scores ----------------
#define FOLD1(Cp, f, ps) do { \
    const int mi_ = (f) >> 4, nj_ = ((f) >> 2) & 3, e_ = (f) & 3; \
    const int rh_ = e_ >> 1; \
    float sv_ = Cp[mi_][nj_][e_]; \
    float lb_; \
    asm volatile("ld.shared.f32 %0, [%1];" : "=f"(lb_) \
        : "r"(sb + SM_LAB + (unsigned)(((unsigned)(ps) * 128u + wn * 32u + nj_ * 8u + ((lane & 3) << 1) + (e_ & 1)) << 2))); \
    rmx[mi_][rh_] = fmaxf(rmx[mi_][rh_], sv_); \
    float ex_ = ex2f(fmaf(sv_, K_EX2A, K_EX2B)); \
    tal[mi_][rh_] += ex_; \
    t1a[mi_][rh_] = fmaf(ex_, lb_, t1a[mi_][rh_]); \
    Cp[mi_][nj_][e_] = 0.f; \
} while (0)

// one step: prefetch next step's B (warp0 lane0) + 16 kt of MMA + interleaved fold
#define STAGE(tcur, sg, Ccur, Cprv, DOFOLD) do { \
    const int buf_ = (tcur) & 1; \
    if (wid == 0 && lane == 0) { \
        const int nt_ = (tcur) + 1; \
        if (nt_ < nsteps) { \
            if (nt_ >= 2) MBAR_WAIT(sb + SM_FREE + 16 * (nt_ & 1), ((nt_ - 2) >> 1) & 1); \
            MBAR_EXPECT_TX(sb + SM_FULL + 16 * (nt_ & 1), BSTAGE_BYTES); \
            const int sgn_ = (((jb + (nt_ >> 3)) & 7) << 3) + (nt_ & 7); \
            BULK_G2S(sb + SM_B + ((unsigned)(nt_ & 1) << 16), \
                     g_Bsw + (size_t)sgn_ * BSTAGE_BYTES, (unsigned)BSTAGE_BYTES, \
                     sb + SM_FULL + 16 * (nt_ & 1)); \
        } \
    } \
    MBAR_WAIT(sb + SM_FULL + 16 * buf_, ((tcur) >> 1) & 1); \
    const unsigned bbase_ = sb + SM_B + ((unsigned)buf_ << 16) + lanoff; \
    _Pragma("unroll") \
    for (int kt_ = 0; kt_ < 16; kt_++) { \
        unsigned Ar0[4], Ar1[4], Bf0[4], Bf1[4]; \
        LDSM4(Ar0, abase  + (unsigned)((kt_ * 8 + wm * 2 + 0) << 9)); \
        LDSM4(Ar1, abase  + (unsigned)((kt_ * 8 + wm * 2 + 1) << 9)); \
        LDSM4(Bf0, bbase_ + (unsigned)((kt_ * 8 + wn * 2 + 0) << 9)); \
        LDSM4(Bf1, bbase_ + (unsigned)((kt_ * 8 + wn * 2 + 1) << 9)); \
        MMA_FP16(Ccur[0][0], Ar0, Bf0[0], Bf0[1]); \
        MMA_FP16(Ccur[0][1], Ar0, Bf0[2], Bf0[3]); \
        MMA_FP16(Ccur[0][2], Ar0, Bf1[0], Bf1[1]); \
        MMA_FP16(Ccur[0][3], Ar0, Bf1[2], Bf1[3]); \
        MMA_FP16(Ccur[1][0], Ar1, Bf0[0], Bf0[1]); \
        MMA_FP16(Ccur[1][1], Ar1, Bf0[2], Bf0[3]); \
        MMA_FP16(Ccur[1][2], Ar1, Bf1[0], Bf1[1]); \
        MMA_FP16(Ccur[1][3], Ar1, Bf1[2], Bf1[3]); \
        if (DOFOLD) { \
            FOLD1(Cprv, kt_ * 2 + 0, (sg) - 1); \
            FOLD1(Cprv, kt_ * 2 + 1, (sg) - 1); \
        } \
    } \
    if (lane == 0) MBAR_ARRIVE(sb + SM_FREE + 16 * buf_); \
} while (0)

// ---------------- main: persistent 148-CTA GEMM over 1008 jobs (R12-identical) ----------------
__global__ __launch_bounds__(512, 1) void contrast_mm() {
    extern __shared__ char smem[];
    const unsigned sb = smem_u32(smem);
    const int tid = threadIdx.x, wid = tid >> 5, lane = tid & 31;
    const int c = blockIdx.x;
    const int jb = (c * NJOBS) / GRIDC, je = ((c + 1) * NJOBS) / GRIDC;
    const int nsteps = (je - jb) * 8;

    if (tid == 0) {
        MBAR_INIT(sb + SM_AF, 1);
        MBAR_INIT(sb + SM_FULL + 0, 1);   MBAR_INIT(sb + SM_FULL + 16, 1);
        MBAR_INIT(sb + SM_FREE + 0, 16);  MBAR_INIT(sb + SM_FREE + 16, 16);
    }
    __syncthreads();
    if (tid == 0) {   // prefetch B for step 0
        MBAR_EXPECT_TX(sb + SM_FULL + 0, BSTAGE_BYTES);
        BULK_G2S(sb + SM_B, g_Bsw + (size_t)((jb & 7) * 8) * BSTAGE_BYTES,
                 (unsigned)BSTAGE_BYTES, sb + SM_FULL + 0);
    }

    const int wm = wid >> 2, wn = wid & 3;   // 4 M-warps x 4 N-warps, tile 32x32
    const unsigned lanoff = (unsigned)(((lane >> 3) << 7) + ((lane & 7) << 4));
    const unsigned abase = sb + SM_A + lanoff;

    float Ca[2][4][4], Cb[2][4][4];
    #pragma unroll
    for (int mi = 0; mi < 2; mi++)
        #pragma unroll
        for (int nj = 0; nj < 4; nj++)
            #pragma unroll
            for (int e = 0; e < 4; e++) { Ca[mi][nj][e] = 0.f; Cb[mi][nj][e] = 0.f; }
    float rmx[2][2], tal[2][2], t1a[2][2];
    #pragma unroll
    for (int mi = 0; mi < 2; mi++)
        #pragma unroll
        for (int rh = 0; rh < 2; rh++) { rmx[mi][rh] = -1e30f; tal[mi][rh] = 0.f; t1a[mi][rh] = 0.f; }

    int aphase = 0, cur_a = -1, cur_mt = -1, t = 0;

    for (int j = jb; j < je; j++) {
        const int a = j / 504, mt = (j % 504) >> 3, ch = j & 7;
        if (a != cur_a || mt != cur_mt) {
            __syncthreads();
            if (tid == 0) {
                const unsigned bytes = (unsigned)ATILE_BYTES + (a != cur_a ? (unsigned)LAB_BYTES : 0u);
                MBAR_EXPECT_TX(sb + SM_AF, bytes);
                BULK_G2S(sb + SM_A, g_Asw[a] + (size_t)mt * ATILE_BYTES,
                         (unsigned)ATILE_BYTES, sb + SM_AF);
                if (a != cur_a)
                    BULK_G2S(sb + SM_LAB, g_alf[a], (unsigned)LAB_BYTES, sb + SM_AF);
            }
            MBAR_WAIT(sb + SM_AF, aphase);
            aphase ^= 1;
            cur_a = a; cur_mt = mt;
        }
        const int sg0 = ch * 8;
        for (int sp = 0; sp < 4; sp++) {
            const bool f0 = (sp > 0);
            STAGE(t,     sg0 + sp * 2,     Ca, Cb, f0);
            STAGE(t + 1, sg0 + sp * 2 + 1, Cb, Ca, true);
            t += 2;
        }
        #pragma unroll
        for (int f = 0; f < 32; f++) FOLD1(Cb, f, sg0 + 7);

        #pragma unroll
        for (int mi = 0; mi < 2; mi++)
            #pragma unroll
            for (int rh = 0; rh < 2; rh++) {
                #pragma unroll
                for (int off = 1; off <= 2; off <<= 1) {
                    rmx[mi][rh] = fmaxf(rmx[mi][rh], __shfl_xor_sync(0xffffffffu, rmx[mi][rh], off));
                    tal[mi][rh] += __shfl_xor_sync(0xffffffffu, tal[mi][rh], off);
                    t1a[mi][rh] += __shfl_xor_sync(0xffffffffu, t1a[mi][rh], off);
                }
            }
        if ((lane & 3) == 0) {
            #pragma unroll
            for (int mi = 0; mi < 2; mi++)
                #pragma unroll
                for (int rh = 0; rh < 2; rh++) {
                    const int rr = wm * 32 + mi * 16 + rh * 8 + (lane >> 2);
                    g_jpart[((size_t)j * 4 + wn) * 128 + rr] =
                        make_float4(rmx[mi][rh], tal[mi][rh], t1a[mi][rh], 0.f);
                }
        }
        #pragma unroll
        for (int mi = 0; mi < 2; mi++)
            #pragma unroll
            for (int rh = 0; rh < 2; rh++) { rmx[mi][rh] = -1e30f; tal[mi][rh] = 0.f; t1a[mi][rh] = 0.f; }
    }
}

// ---------------- combine (+ fused last-block finalize) ----------------
__global__ void combine(const float* __restrict__ plog1, const float* __restrict__ plog2,
                        float* __restrict__ out) {
    __shared__ float sm[4][2];
    __shared__ int is_last;
    const int x = blockIdx.x;            // 0..125
    const int a = x / MTILES, mt = x % MTILES;
    const int row = threadIdx.x;         // 128
    const int lane = row & 31;

    float rmax = -1e30f, tall = 0.f, t1v = 0.f;
    const size_t jbase = ((size_t)a * 504 + (size_t)mt * 8) * 4 * 128;
    #pragma unroll
    for (int ch = 0; ch < 8; ch++)
        #pragma unroll
        for (int wn = 0; wn < 4; wn++) {
            float4 v = g_jpart[jbase + ((size_t)ch * 4 + wn) * 128 + row];
            rmax = fmaxf(rmax, v.x);
            tall += v.y;
            t1v  += v.z;
        }
    tall -= (float)(NPADN - NROWS) * ex2f(K_EX2B);

    float num = 0.f, cnt = 0.f;
    const int i = mt * MT + row;
    if (i < NROWS) {
        float posv = g_pos[i];
        float mfull = fmaxf(rmax * 10.f, posv);
        float tsel = (g_memlab[i] == 0.f) ? t1v : (tall - t1v);
        float epos = __expf(posv - mfull);
        float sum = epos + tsel * __expf(12.f - mfull);
        float lossv = -logf(epos / (sum + 1e-8f) + 1e-8f);
        float q1 = plog1[i], q2 = plog2[i];
        float mask = a ? ((q1 > 0.7f && q2 < q1) ? 1.f : 0.f)
                       : ((q2 > 0.7f && q1 < q2) ? 1.f : 0.f);
        num = lossv * mask;
        cnt = mask;
    }
    #pragma unroll
    for (int o = 16; o > 0; o >>= 1) {
        num += __shfl_xor_sync(0xffffffffu, num, o);
        cnt += __shfl_xor_sync(0xffffffffu, cnt, o);
    }
    if (lane == 0) { sm[row >> 5][0] = num; sm[row >> 5][1] = cnt; }
    __syncthreads();
    if (row == 0) {
        float n = sm[0][0] + sm[1][0] + sm[2][0] + sm[3][0];
        float cc = sm[0][1] + sm[1][1] + sm[2][1] + sm[3][1];
        g_part[a][mt] = make_float2(n, cc);
        __threadfence();
        is_last = (atomicAdd(&g_combc, 1) == 2 * MTILES - 1);
    }
    __syncthreads();
    if (is_last) {
        __threadfence();   // acquire: all g_part writes visible
        const int aa = row >> 6, idx = row & 63;
        float n = 0.f, cc = 0.f;
        if (idx < MTILES) { float2 v = g_part[aa][idx]; n = v.x; cc = v.y; }
        #pragma unroll
        for (int o = 16; o > 0; o >>= 1) {
            n += __shfl_xor_sync(0xffffffffu, n, o);
            cc += __shfl_xor_sync(0xffffffffu, cc, o);
        }
        __syncthreads();
        if (lane == 0) { sm[row >> 5][0] = n; sm[row >> 5][1] = cc; }
        __syncthreads();
        if (row == 0) {
            float n1 = sm[0][0] + sm[1][0], c1 = sm[0][1] + sm[1][1];
            float n2 = sm[2][0] + sm[3][0], c2 = sm[2][1] + sm[3][1];
            out[0] = n1 / (c1 + 1e-12f) + n2 / (c2 + 1e-12f);
        }
    }
}

// ---------------- launch ----------------
extern "C" void kernel_launch(void* const* d_in, const int* in_sizes, int n_in,
                              void* d_out, int out_size) {
    const float* feat1 = (const float*)d_in[0];
    const float* feat2 = (const float*)d_in[1];
    const float* ul1   = (const float*)d_in[2];
    const float* ul2   = (const float*)d_in[3];
    const int*   pl1   = (const int*)d_in[4];
    const int*   pl2   = (const int*)d_in[5];
    const float* plog1 = (const float*)d_in[6];
    const float* plog2 = (const float*)d_in[7];
    const int*   sel1  = (const int*)d_in[8];
    const int*   sel2  = (const int*)d_in[9];
    float* out = (float*)d_out;

    cudaFuncSetAttribute(contrast_mm, cudaFuncAttributeMaxDynamicSharedMemorySize, SMEM_TOTAL);

    prep1<<<6048, 256>>>(feat1, feat2, ul1, ul2, sel1, sel2, pl1, pl2);
    prep_B<<<2048, 256>>>(sel1, sel2);
    contrast_mm<<<GRIDC, 512, SMEM_TOTAL>>>();
    combine<<<2 * MTILES, 128>>>(plog1, plog2, out);
}